// round 3
// baseline (speedup 1.0000x reference)
#include <cuda_runtime.h>
#include <math_constants.h>

// Problem constants (OnlineTripletLoss: B=8192, D=512)
#define BDIM 8192
#define DDIM 512

// GEMM tiling
#define BM 64
#define BN 64
#define BK 32
#define NSPLIT 4
#define JCHUNK (BDIM / NSPLIT)   // 2048 columns per block

// Scratch (device globals: allocation-free per harness rules)
__device__ __align__(16) float g_An[BDIM * DDIM];
__device__ __align__(16) float g_Pn[BDIM * DDIM];
__device__ float g_diag[BDIM];
__device__ float g_pmin[NSPLIT * BDIM];

// ---------------------------------------------------------------------------
// Kernel 1: row-normalize anchor & positive, compute diag cosine a_n.p_n
// one block per row, 128 threads
// ---------------------------------------------------------------------------
__global__ void normalize_diag_kernel(const float* __restrict__ A,
                                      const float* __restrict__ P) {
    const int row = blockIdx.x;
    const int t = threadIdx.x;           // 128 threads
    const float* a = A + (size_t)row * DDIM;
    const float* p = P + (size_t)row * DDIM;

    float sa = 0.f, sp = 0.f, sap = 0.f;
    #pragma unroll
    for (int k = t; k < DDIM; k += 128) {
        float av = a[k], pv = p[k];
        sa += av * av;
        sp += pv * pv;
        sap += av * pv;
    }
    // warp reduce
    #pragma unroll
    for (int off = 16; off >= 1; off >>= 1) {
        sa  += __shfl_xor_sync(0xffffffff, sa, off);
        sp  += __shfl_xor_sync(0xffffffff, sp, off);
        sap += __shfl_xor_sync(0xffffffff, sap, off);
    }
    __shared__ float red[3][4];
    const int warp = t >> 5, lane = t & 31;
    if (lane == 0) { red[0][warp] = sa; red[1][warp] = sp; red[2][warp] = sap; }
    __syncthreads();
    float tsa  = red[0][0] + red[0][1] + red[0][2] + red[0][3];
    float tsp  = red[1][0] + red[1][1] + red[1][2] + red[1][3];
    float tsap = red[2][0] + red[2][1] + red[2][2] + red[2][3];

    const float inva = rsqrtf(tsa);
    const float invp = rsqrtf(tsp);
    float* an = g_An + (size_t)row * DDIM;
    float* pn = g_Pn + (size_t)row * DDIM;
    #pragma unroll
    for (int k = t; k < DDIM; k += 128) {
        an[k] = a[k] * inva;
        pn[k] = p[k] * invp;
    }
    if (t == 0) g_diag[row] = tsap * inva * invp;
}

// ---------------------------------------------------------------------------
// Kernel 2: fused sim = An @ Pn^T with running row-min over j != i.
// grid: (NSPLIT, BDIM/BM). 256 threads, 16x16 thread grid, 4x4 micro-tile.
// ---------------------------------------------------------------------------
__global__ __launch_bounds__(256, 4)
void gemm_min_kernel() {
    __shared__ float As[BK][BM + 4];
    __shared__ float Ps[BK][BN + 4];

    const int tid = threadIdx.x;
    const int tr = tid >> 4;     // 0..15 -> rows tr*4 .. tr*4+3
    const int tc = tid & 15;     // 0..15 -> cols tc*4 .. tc*4+3
    const int iBase = blockIdx.y * BM;
    const int jChunkBase = blockIdx.x * JCHUNK;

    // loader indexing: each thread loads two float4 along k for A and for P
    const int lr = tid >> 3;           // 0..31
    const int lk = (tid & 7) * 4;      // 0,4,...,28

    float rowmin[4] = {CUDART_INF_F, CUDART_INF_F, CUDART_INF_F, CUDART_INF_F};

    for (int jt = 0; jt < JCHUNK; jt += BN) {
        const int jBase = jChunkBase + jt;
        float acc[4][4];
        #pragma unroll
        for (int m = 0; m < 4; m++)
            #pragma unroll
            for (int n = 0; n < 4; n++)
                acc[m][n] = 0.f;

        for (int k0 = 0; k0 < DDIM; k0 += BK) {
            // load A tile (64 x 32) transposed into As[k][r]
            {
                const float4 v0 = *(const float4*)&g_An[(size_t)(iBase + lr) * DDIM + k0 + lk];
                const float4 v1 = *(const float4*)&g_An[(size_t)(iBase + lr + 32) * DDIM + k0 + lk];
                As[lk + 0][lr] = v0.x; As[lk + 1][lr] = v0.y;
                As[lk + 2][lr] = v0.z; As[lk + 3][lr] = v0.w;
                As[lk + 0][lr + 32] = v1.x; As[lk + 1][lr + 32] = v1.y;
                As[lk + 2][lr + 32] = v1.z; As[lk + 3][lr + 32] = v1.w;
            }
            // load P tile (64 x 32) transposed into Ps[k][c]
            {
                const float4 v0 = *(const float4*)&g_Pn[(size_t)(jBase + lr) * DDIM + k0 + lk];
                const float4 v1 = *(const float4*)&g_Pn[(size_t)(jBase + lr + 32) * DDIM + k0 + lk];
                Ps[lk + 0][lr] = v0.x; Ps[lk + 1][lr] = v0.y;
                Ps[lk + 2][lr] = v0.z; Ps[lk + 3][lr] = v0.w;
                Ps[lk + 0][lr + 32] = v1.x; Ps[lk + 1][lr + 32] = v1.y;
                Ps[lk + 2][lr + 32] = v1.z; Ps[lk + 3][lr + 32] = v1.w;
            }
            __syncthreads();

            #pragma unroll
            for (int k = 0; k < BK; k++) {
                const float4 a = *(const float4*)&As[k][tr * 4];
                const float4 p = *(const float4*)&Ps[k][tc * 4];
                acc[0][0] += a.x * p.x; acc[0][1] += a.x * p.y;
                acc[0][2] += a.x * p.z; acc[0][3] += a.x * p.w;
                acc[1][0] += a.y * p.x; acc[1][1] += a.y * p.y;
                acc[1][2] += a.y * p.z; acc[1][3] += a.y * p.w;
                acc[2][0] += a.z * p.x; acc[2][1] += a.z * p.y;
                acc[2][2] += a.z * p.z; acc[2][3] += a.z * p.w;
                acc[3][0] += a.w * p.x; acc[3][1] += a.w * p.y;
                acc[3][2] += a.w * p.z; acc[3][3] += a.w * p.w;
            }
            __syncthreads();
        }

        // update running min, excluding the diagonal entry
        #pragma unroll
        for (int m = 0; m < 4; m++) {
            const int gi = iBase + tr * 4 + m;
            #pragma unroll
            for (int n = 0; n < 4; n++) {
                const int gj = jBase + tc * 4 + n;
                const float v = (gi == gj) ? CUDART_INF_F : acc[m][n];
                rowmin[m] = fminf(rowmin[m], v);
            }
        }
    }

    // reduce min across the 16 tc-threads holding the same rows.
    // tc occupies bits [0:4) of tid => lanes differing in bits 0..3 share rows.
    #pragma unroll
    for (int m = 0; m < 4; m++) {
        float v = rowmin[m];
        #pragma unroll
        for (int off = 8; off >= 1; off >>= 1)
            v = fminf(v, __shfl_xor_sync(0xffffffff, v, off));
        if (tc == 0)
            g_pmin[(size_t)blockIdx.x * BDIM + iBase + tr * 4 + m] = v;
    }
}

// ---------------------------------------------------------------------------
// Kernel 3: combine partial mins, compute mean relu(1 + diag - min)
// single block
// ---------------------------------------------------------------------------
__global__ void final_loss_kernel(float* __restrict__ out) {
    const int t = threadIdx.x;   // 256
    float sum = 0.f;
    for (int i = t; i < BDIM; i += 256) {
        float m = g_pmin[i];
        #pragma unroll
        for (int s = 1; s < NSPLIT; s++)
            m = fminf(m, g_pmin[s * BDIM + i]);
        const float l = 1.0f + g_diag[i] - m;
        sum += (l > 0.f) ? l : 0.f;
    }
    #pragma unroll
    for (int off = 16; off >= 1; off >>= 1)
        sum += __shfl_xor_sync(0xffffffff, sum, off);
    __shared__ float red[8];
    const int warp = t >> 5, lane = t & 31;
    if (lane == 0) red[warp] = sum;
    __syncthreads();
    if (t == 0) {
        float total = 0.f;
        #pragma unroll
        for (int w = 0; w < 8; w++) total += red[w];
        out[0] = total / (float)BDIM;
    }
}

// ---------------------------------------------------------------------------
extern "C" void kernel_launch(void* const* d_in, const int* in_sizes, int n_in,
                              void* d_out, int out_size) {
    const float* anchor   = (const float*)d_in[0];
    const float* positive = (const float*)d_in[1];
    float* out = (float*)d_out;

    normalize_diag_kernel<<<BDIM, 128>>>(anchor, positive);
    dim3 grid(NSPLIT, BDIM / BM);
    gemm_min_kernel<<<grid, 256>>>();
    final_loss_kernel<<<1, 256>>>(out);
}

// round 5
// speedup vs baseline: 12.1560x; 12.1560x over previous
#include <cuda_runtime.h>
#include <cuda_fp16.h>
#include <math_constants.h>
#include <cstdint>

// Problem constants (OnlineTripletLoss: B=8192, D=512)
#define BDIM 8192
#define DDIM 512

// GEMM tiling (fp16 mma.sync path — tcgen05 unavailable on compute_103 target)
#define BM 128
#define BN 128
#define BKH 64                       // halves per k-tile = 128 bytes/row (SW128 atom)
#define KTILES (DDIM / BKH)          // 8
#define TILEB (128 * 128)            // one operand tile: 128 rows x 128 bytes
#define STAGEB (2 * TILEB)           // A + P = 32 KB
#define SMEMB (2 * STAGEB)           // double buffered = 64 KB

// Scratch (device globals: allocation-free per harness rules)
__device__ __align__(16) __half g_A[BDIM * DDIM];
__device__ __align__(16) __half g_P[BDIM * DDIM];
__device__ float g_diag[BDIM];
__device__ unsigned int g_minenc[BDIM];

// ---------------------------------------------------------------------------
// helpers
// ---------------------------------------------------------------------------
__device__ __forceinline__ uint32_t smem_u32(const void* p) {
    uint32_t a;
    asm("{ .reg .u64 t; cvta.to.shared.u64 t, %1; cvt.u32.u64 %0, t; }" : "=r"(a) : "l"(p));
    return a;
}

__device__ __forceinline__ uint32_t sw128(uint32_t off) {
    return off ^ ((off >> 3) & 0x70);
}

__device__ __forceinline__ void cp_async16(uint32_t dst, const void* src) {
    asm volatile("cp.async.cg.shared.global [%0], [%1], 16;" :: "r"(dst), "l"(src) : "memory");
}

__device__ __forceinline__ void ldsm_x4(uint32_t* r, uint32_t addr) {
    asm volatile("ldmatrix.sync.aligned.m8n8.x4.shared.b16 {%0,%1,%2,%3}, [%4];"
                 : "=r"(r[0]), "=r"(r[1]), "=r"(r[2]), "=r"(r[3]) : "r"(addr));
}

__device__ __forceinline__ void mma16816(float* c, const uint32_t* a,
                                         uint32_t b0, uint32_t b1) {
    asm volatile(
        "mma.sync.aligned.m16n8k16.row.col.f32.f16.f16.f32 "
        "{%0,%1,%2,%3}, {%4,%5,%6,%7}, {%8,%9}, {%0,%1,%2,%3};"
        : "+f"(c[0]), "+f"(c[1]), "+f"(c[2]), "+f"(c[3])
        : "r"(a[0]), "r"(a[1]), "r"(a[2]), "r"(a[3]), "r"(b0), "r"(b1));
}

// monotonic unsigned encoding of float for atomicMin
__device__ __forceinline__ unsigned int enc_f32(float v) {
    unsigned int b = __float_as_uint(v);
    return (b & 0x80000000u) ? ~b : (b ^ 0x80000000u);
}
__device__ __forceinline__ float dec_f32(unsigned int e) {
    unsigned int b = (e & 0x80000000u) ? (e ^ 0x80000000u) : ~e;
    return __uint_as_float(b);
}

// ---------------------------------------------------------------------------
// Kernel 1: row-normalize -> fp16, diag cosine (exact fp32), min-enc init
// ---------------------------------------------------------------------------
__global__ void normalize_diag_kernel(const float* __restrict__ A,
                                      const float* __restrict__ P) {
    const int row = blockIdx.x;
    const int t = threadIdx.x;           // 128 threads
    const float* a = A + (size_t)row * DDIM;
    const float* p = P + (size_t)row * DDIM;

    float sa = 0.f, sp = 0.f, sap = 0.f;
    #pragma unroll
    for (int k = t; k < DDIM; k += 128) {
        float av = a[k], pv = p[k];
        sa += av * av;
        sp += pv * pv;
        sap += av * pv;
    }
    #pragma unroll
    for (int off = 16; off >= 1; off >>= 1) {
        sa  += __shfl_xor_sync(0xffffffff, sa, off);
        sp  += __shfl_xor_sync(0xffffffff, sp, off);
        sap += __shfl_xor_sync(0xffffffff, sap, off);
    }
    __shared__ float red[3][4];
    const int warp = t >> 5, lane = t & 31;
    if (lane == 0) { red[0][warp] = sa; red[1][warp] = sp; red[2][warp] = sap; }
    __syncthreads();
    float tsa  = red[0][0] + red[0][1] + red[0][2] + red[0][3];
    float tsp  = red[1][0] + red[1][1] + red[1][2] + red[1][3];
    float tsap = red[2][0] + red[2][1] + red[2][2] + red[2][3];

    const float inva = rsqrtf(tsa);
    const float invp = rsqrtf(tsp);
    #pragma unroll
    for (int k = t; k < DDIM; k += 128) {
        const size_t idx = (size_t)row * DDIM + k;
        g_A[idx] = __float2half_rn(a[k] * inva);
        g_P[idx] = __float2half_rn(p[k] * invp);
    }
    if (t == 0) {
        g_diag[row] = tsap * inva * invp;
        g_minenc[row] = 0xFFFFFFFFu;
    }
}

// ---------------------------------------------------------------------------
// Kernel 2: fp16 mma.sync fused GEMM + diagonal-masked row-min.
// grid (64, 64): one 128x128 sim tile per CTA. 8 warps, warp tile 64x32.
// ---------------------------------------------------------------------------
__global__ __launch_bounds__(256, 2)
void gemm_min_mma() {
    extern __shared__ __align__(1024) char dyn[];

    const int tid = threadIdx.x;
    const int warp = tid >> 5;
    const int lane = tid & 31;
    const int wm = warp & 1;           // 2 warp-rows of 64
    const int wn = warp >> 1;          // 4 warp-cols of 32
    const int iBase = blockIdx.y * BM;
    const int jBase = blockIdx.x * BN;

    const uint32_t smem = smem_u32(dyn);

    float acc[4][4][4];
    #pragma unroll
    for (int mi = 0; mi < 4; mi++)
        #pragma unroll
        for (int ni = 0; ni < 4; ni++)
            #pragma unroll
            for (int q = 0; q < 4; q++)
                acc[mi][ni][q] = 0.f;

    // loader: each stage = A tile (1024 x 16B) + P tile (1024 x 16B), 8 segs/thread
    auto load_stage = [&](int buf, int kt) {
        const uint32_t sbase = smem + buf * STAGEB;
        #pragma unroll
        for (int r = 0; r < 4; r++) {
            const int s = tid + 256 * r;            // 0..1023
            const int row = s >> 3;
            const int seg = s & 7;
            const uint32_t dstoff = sw128(row * 128 + seg * 16);
            cp_async16(sbase + dstoff,
                       g_A + (size_t)(iBase + row) * DDIM + kt * BKH + seg * 8);
            cp_async16(sbase + TILEB + dstoff,
                       g_P + (size_t)(jBase + row) * DDIM + kt * BKH + seg * 8);
        }
        asm volatile("cp.async.commit_group;" ::: "memory");
    };

    auto compute_stage = [&](int buf) {
        const uint32_t aBase = smem + buf * STAGEB;
        const uint32_t pBase = aBase + TILEB;
        const int lrow = lane & 15;          // ldmatrix source row within 16
        const int lcol = (lane >> 4) * 16;   // 0 or 16 bytes (k halves 0-7 / 8-15)
        #pragma unroll
        for (int ks = 0; ks < 4; ks++) {
            uint32_t af[4][4];
            #pragma unroll
            for (int mi = 0; mi < 4; mi++) {
                const int row = wm * 64 + mi * 16 + lrow;
                ldsm_x4(af[mi], aBase + sw128(row * 128 + ks * 32 + lcol));
            }
            uint32_t bf[2][4];
            #pragma unroll
            for (int nh = 0; nh < 2; nh++) {
                const int row = wn * 32 + nh * 16 + lrow;
                ldsm_x4(bf[nh], pBase + sw128(row * 128 + ks * 32 + lcol));
            }
            #pragma unroll
            for (int mi = 0; mi < 4; mi++) {
                #pragma unroll
                for (int ni = 0; ni < 4; ni++) {
                    const int nh = ni >> 1, sel = ni & 1;
                    mma16816(acc[mi][ni], af[mi], bf[nh][sel], bf[nh][sel + 2]);
                }
            }
        }
    };

    // 2-stage cp.async pipeline
    load_stage(0, 0);
    for (int kt = 0; kt < KTILES; kt++) {
        const int b = kt & 1;
        if (kt + 1 < KTILES) {
            load_stage(b ^ 1, kt + 1);
            asm volatile("cp.async.wait_group 1;" ::: "memory");
        } else {
            asm volatile("cp.async.wait_group 0;" ::: "memory");
        }
        __syncthreads();
        compute_stage(b);
        __syncthreads();
    }

    // epilogue: diagonal-masked row-min, lane-quad reduce, global atomicMin
    #pragma unroll
    for (int mi = 0; mi < 4; mi++) {
        #pragma unroll
        for (int half = 0; half < 2; half++) {
            const int gi = iBase + wm * 64 + mi * 16 + (lane >> 2) + half * 8;
            float vmin = CUDART_INF_F;
            #pragma unroll
            for (int ni = 0; ni < 4; ni++) {
                const int gj0 = jBase + wn * 32 + ni * 8 + 2 * (lane & 3);
                const float v0 = (gi == gj0)     ? CUDART_INF_F : acc[mi][ni][half * 2 + 0];
                const float v1 = (gi == gj0 + 1) ? CUDART_INF_F : acc[mi][ni][half * 2 + 1];
                vmin = fminf(vmin, fminf(v0, v1));
            }
            vmin = fminf(vmin, __shfl_xor_sync(0xffffffff, vmin, 1));
            vmin = fminf(vmin, __shfl_xor_sync(0xffffffff, vmin, 2));
            if ((lane & 3) == 0)
                atomicMin(&g_minenc[gi], enc_f32(vmin));
        }
    }
}

// ---------------------------------------------------------------------------
// Kernel 3: decode per-row min, compute mean relu(1 + diag - min)
// ---------------------------------------------------------------------------
__global__ void final_loss_kernel(float* __restrict__ out) {
    const int t = threadIdx.x;   // 256
    float sum = 0.f;
    for (int i = t; i < BDIM; i += 256) {
        const float m = dec_f32(g_minenc[i]);
        const float l = 1.0f + g_diag[i] - m;
        sum += (l > 0.f) ? l : 0.f;
    }
    #pragma unroll
    for (int off = 16; off >= 1; off >>= 1)
        sum += __shfl_xor_sync(0xffffffff, sum, off);
    __shared__ float red[8];
    const int warp = t >> 5, lane = t & 31;
    if (lane == 0) red[warp] = sum;
    __syncthreads();
    if (t == 0) {
        float total = 0.f;
        #pragma unroll
        for (int w = 0; w < 8; w++) total += red[w];
        out[0] = total / (float)BDIM;
    }
}

// ---------------------------------------------------------------------------
extern "C" void kernel_launch(void* const* d_in, const int* in_sizes, int n_in,
                              void* d_out, int out_size) {
    const float* anchor   = (const float*)d_in[0];
    const float* positive = (const float*)d_in[1];
    float* out = (float*)d_out;

    cudaFuncSetAttribute(gemm_min_mma, cudaFuncAttributeMaxDynamicSharedMemorySize, SMEMB);

    normalize_diag_kernel<<<BDIM, 128>>>(anchor, positive);
    dim3 grid(BDIM / BN, BDIM / BM);
    gemm_min_mma<<<grid, 256, SMEMB>>>();
    final_loss_kernel<<<1, 256>>>(out);
}